// round 3
// baseline (speedup 1.0000x reference)
#include <cuda_runtime.h>
#include <math.h>

#define NN 50000
#define NE 800000
#define DIM 128
#define DOUT 64

// ---- scratch (device globals: allocation-free) ----
__device__ float g_agg[NN * DIM];
__device__ float g_h0[NN * DIM];
__device__ float g_h1[NN * DIM];
__device__ int   g_cnt[NN];
__device__ int   g_rowstart[NN + 1];
__device__ int   g_cursor[NN];
__device__ int   g_srcs[NE];

// ---------------- CSR build ----------------
__global__ void k_zero_cnt(int n) {
    int i = blockIdx.x * blockDim.x + threadIdx.x;
    if (i < n) g_cnt[i] = 0;
}

__global__ void k_hist(const int* __restrict__ dst, int E) {
    int e = blockIdx.x * blockDim.x + threadIdx.x;
    if (e < E) atomicAdd(&g_cnt[dst[e]], 1);
}

// single-block scan over n counts -> exclusive rowstart, plus cursor copy
__global__ void k_scan(int n) {
    __shared__ int wsum[32];
    const int tid = threadIdx.x, lane = tid & 31, wid = tid >> 5;
    int carry = 0;
    for (int base = 0; base < n; base += 1024) {
        int i = base + tid;
        int v = (i < n) ? g_cnt[i] : 0;
        int incl = v;
        #pragma unroll
        for (int o = 1; o < 32; o <<= 1) {
            int t = __shfl_up_sync(0xffffffffu, incl, o);
            if (lane >= o) incl += t;
        }
        if (lane == 31) wsum[wid] = incl;
        __syncthreads();
        if (wid == 0) {
            int s = wsum[lane];
            #pragma unroll
            for (int o = 1; o < 32; o <<= 1) {
                int t = __shfl_up_sync(0xffffffffu, s, o);
                if (lane >= o) s += t;
            }
            wsum[lane] = s;
        }
        __syncthreads();
        int excl = carry + (wid > 0 ? wsum[wid - 1] : 0) + incl - v;
        if (i < n) { g_rowstart[i] = excl; g_cursor[i] = excl; }
        int total = wsum[31];
        __syncthreads();
        carry += total;
    }
    if (tid == 0) g_rowstart[n] = carry;
}

__global__ void k_scatter(const int* __restrict__ src, const int* __restrict__ dst, int E) {
    int e = blockIdx.x * blockDim.x + threadIdx.x;
    if (e < E) {
        int p = atomicAdd(&g_cursor[dst[e]], 1);
        g_srcs[p] = src[e];
    }
}

// ---------------- mean aggregation (pull, warp per node, no fp atomics) ----------------
__global__ void k_agg(const float* __restrict__ in, float* __restrict__ outm, int n) {
    int w = (blockIdx.x * blockDim.x + threadIdx.x) >> 5;
    int lane = threadIdx.x & 31;
    if (w >= n) return;
    int rs = g_rowstart[w], re = g_rowstart[w + 1];
    float4 acc = make_float4(0.f, 0.f, 0.f, 0.f);
    for (int j = rs; j < re;) {
        int c = min(32, re - j);
        int s = (lane < c) ? g_srcs[j + lane] : 0;
        #pragma unroll 4
        for (int i = 0; i < c; i++) {
            int si = __shfl_sync(0xffffffffu, s, i);
            float4 v = *(const float4*)(in + (size_t)si * DIM + lane * 4);
            acc.x += v.x; acc.y += v.y; acc.z += v.z; acc.w += v.w;
        }
        j += c;
    }
    int deg = re - rs;
    float sc = deg > 0 ? 1.0f / (float)deg : 0.0f;
    acc.x *= sc; acc.y *= sc; acc.z *= sc; acc.w *= sc;
    *(float4*)(outm + (size_t)w * DIM + lane * 4) = acc;
}

// ---------------- fused dual-GEMM + bias + relu (layers 0/1, 128->128) ----------------
// out[r, :] = relu( A1[r,:] @ Wl + A2[r,:] @ Wr + b )
__global__ void __launch_bounds__(256) k_gemm_relu(
    const float* __restrict__ A1, const float* __restrict__ A2,
    const float* __restrict__ Wl, const float* __restrict__ Wr,
    const float* __restrict__ b,  float* __restrict__ out, int n)
{
    extern __shared__ float sm[];
    float* sWl = sm;
    float* sWr = sWl + DIM * DIM;
    float* sA1 = sWr + DIM * DIM;
    float* sA2 = sA1 + 64 * DIM;
    const int tid = threadIdx.x;
    const int row0 = blockIdx.x * 64;

    for (int i = tid * 4; i < DIM * DIM; i += 1024) {
        *(float4*)(sWl + i) = *(const float4*)(Wl + i);
        *(float4*)(sWr + i) = *(const float4*)(Wr + i);
    }
    float4 z = make_float4(0.f, 0.f, 0.f, 0.f);
    for (int i = tid * 4; i < 64 * DIM; i += 1024) {
        int r = i >> 7, c = i & 127;
        int gr = row0 + r;
        *(float4*)(sA1 + i) = (gr < n) ? *(const float4*)(A1 + (size_t)gr * DIM + c) : z;
        *(float4*)(sA2 + i) = (gr < n) ? *(const float4*)(A2 + (size_t)gr * DIM + c) : z;
    }
    __syncthreads();

    const int rowg = tid >> 4;   // 0..15 (4 rows each)
    const int colg = tid & 15;   // 0..15 (8 cols each)
    float acc[4][8] = {};
    float a1f[4][4], a2f[4][4], wl[8], wr[8];

    #pragma unroll 2
    for (int k = 0; k < DIM; k += 4) {
        #pragma unroll
        for (int r = 0; r < 4; r++) {
            *(float4*)a1f[r] = *(float4*)(sA1 + (rowg * 4 + r) * DIM + k);
            *(float4*)a2f[r] = *(float4*)(sA2 + (rowg * 4 + r) * DIM + k);
        }
        #pragma unroll
        for (int kk = 0; kk < 4; kk++) {
            *(float4*)(wl)     = *(float4*)(sWl + (k + kk) * DIM + colg * 8);
            *(float4*)(wl + 4) = *(float4*)(sWl + (k + kk) * DIM + colg * 8 + 4);
            *(float4*)(wr)     = *(float4*)(sWr + (k + kk) * DIM + colg * 8);
            *(float4*)(wr + 4) = *(float4*)(sWr + (k + kk) * DIM + colg * 8 + 4);
            #pragma unroll
            for (int r = 0; r < 4; r++) {
                #pragma unroll
                for (int j = 0; j < 8; j++)
                    acc[r][j] += a1f[r][kk] * wl[j] + a2f[r][kk] * wr[j];
            }
        }
    }

    #pragma unroll
    for (int r = 0; r < 4; r++) {
        int gr = row0 + rowg * 4 + r;
        if (gr < n) {
            float o[8];
            #pragma unroll
            for (int j = 0; j < 8; j++) {
                float v = acc[r][j] + b[colg * 8 + j];
                o[j] = fmaxf(v, 0.0f);
            }
            *(float4*)(out + (size_t)gr * DIM + colg * 8)     = *(float4*)o;
            *(float4*)(out + (size_t)gr * DIM + colg * 8 + 4) = *(float4*)(o + 4);
        }
    }
}

// ---------------- final layer: dual-GEMM (128->64) + bias + log_softmax ----------------
__global__ void __launch_bounds__(256) k_gemm_final(
    const float* __restrict__ A1, const float* __restrict__ A2,
    const float* __restrict__ Wl, const float* __restrict__ Wr,
    const float* __restrict__ b,
    float* __restrict__ out_ls, float* __restrict__ out_h, int n)
{
    extern __shared__ float sm[];
    float* sWl = sm;
    float* sWr = sWl + DIM * DOUT;
    float* sA1 = sWr + DIM * DOUT;
    float* sA2 = sA1 + 64 * DIM;
    const int tid = threadIdx.x;
    const int row0 = blockIdx.x * 64;

    for (int i = tid * 4; i < DIM * DOUT; i += 1024) {
        *(float4*)(sWl + i) = *(const float4*)(Wl + i);
        *(float4*)(sWr + i) = *(const float4*)(Wr + i);
    }
    float4 z = make_float4(0.f, 0.f, 0.f, 0.f);
    for (int i = tid * 4; i < 64 * DIM; i += 1024) {
        int r = i >> 7, c = i & 127;
        int gr = row0 + r;
        *(float4*)(sA1 + i) = (gr < n) ? *(const float4*)(A1 + (size_t)gr * DIM + c) : z;
        *(float4*)(sA2 + i) = (gr < n) ? *(const float4*)(A2 + (size_t)gr * DIM + c) : z;
    }
    __syncthreads();

    const int rowg = tid >> 4;   // 4 rows each
    const int colg = tid & 15;   // 4 cols each
    float acc[4][4] = {};
    float a1f[4][4], a2f[4][4], wl[4], wr[4];

    #pragma unroll 2
    for (int k = 0; k < DIM; k += 4) {
        #pragma unroll
        for (int r = 0; r < 4; r++) {
            *(float4*)a1f[r] = *(float4*)(sA1 + (rowg * 4 + r) * DIM + k);
            *(float4*)a2f[r] = *(float4*)(sA2 + (rowg * 4 + r) * DIM + k);
        }
        #pragma unroll
        for (int kk = 0; kk < 4; kk++) {
            *(float4*)wl = *(float4*)(sWl + (k + kk) * DOUT + colg * 4);
            *(float4*)wr = *(float4*)(sWr + (k + kk) * DOUT + colg * 4);
            #pragma unroll
            for (int r = 0; r < 4; r++) {
                #pragma unroll
                for (int j = 0; j < 4; j++)
                    acc[r][j] += a1f[r][kk] * wl[j] + a2f[r][kk] * wr[j];
            }
        }
    }

    // bias + log_softmax over the 64-wide row (split across 16 consecutive lanes)
    #pragma unroll
    for (int r = 0; r < 4; r++) {
        float hv[4];
        #pragma unroll
        for (int j = 0; j < 4; j++) hv[j] = acc[r][j] + b[colg * 4 + j];

        float m = fmaxf(fmaxf(hv[0], hv[1]), fmaxf(hv[2], hv[3]));
        #pragma unroll
        for (int o = 1; o < 16; o <<= 1)
            m = fmaxf(m, __shfl_xor_sync(0xffffffffu, m, o, 16));

        float s = 0.f;
        #pragma unroll
        for (int j = 0; j < 4; j++) s += expf(hv[j] - m);
        #pragma unroll
        for (int o = 1; o < 16; o <<= 1)
            s += __shfl_xor_sync(0xffffffffu, s, o, 16);

        float lse = m + logf(s);

        int gr = row0 + rowg * 4 + r;
        if (gr < n) {
            float ls[4];
            #pragma unroll
            for (int j = 0; j < 4; j++) ls[j] = hv[j] - lse;
            *(float4*)(out_ls + (size_t)gr * DOUT + colg * 4) = *(float4*)ls;
            if (out_h)
                *(float4*)(out_h + (size_t)gr * DOUT + colg * 4) = *(float4*)hv;
        }
    }
}

// ---------------- driver ----------------
extern "C" void kernel_launch(void* const* d_in, const int* in_sizes, int n_in,
                              void* d_out, int out_size) {
    const float* x   = (const float*)d_in[0];
    const int*   ei  = (const int*)d_in[1];
    const float* Wl0 = (const float*)d_in[2];
    const float* Wr0 = (const float*)d_in[3];
    const float* b0  = (const float*)d_in[4];
    const float* Wl1 = (const float*)d_in[5];
    const float* Wr1 = (const float*)d_in[6];
    const float* b1  = (const float*)d_in[7];
    const float* Wl2 = (const float*)d_in[8];
    const float* Wr2 = (const float*)d_in[9];
    const float* b2  = (const float*)d_in[10];

    int n = in_sizes[0] / DIM;   // 50000
    int E = in_sizes[1] / 2;     // 800000
    const int* src = ei;
    const int* dst = ei + E;

    float *agg, *h0, *h1;
    cudaGetSymbolAddress((void**)&agg, g_agg);
    cudaGetSymbolAddress((void**)&h0,  g_h0);
    cudaGetSymbolAddress((void**)&h1,  g_h1);

    float* out_ls = (float*)d_out;
    float* out_h  = (out_size >= 2 * n * DOUT) ? out_ls + (size_t)n * DOUT : nullptr;

    // CSR build
    k_zero_cnt<<<(n + 255) / 256, 256>>>(n);
    k_hist<<<(E + 255) / 256, 256>>>(dst, E);
    k_scan<<<1, 1024>>>(n);
    k_scatter<<<(E + 255) / 256, 256>>>(src, dst, E);

    const int aggBlocks  = (n * 32 + 255) / 256;
    const int gemmBlocks = (n + 63) / 64;
    const size_t smemRelu  = (size_t)(2 * DIM * DIM + 2 * 64 * DIM) * sizeof(float);   // 196608
    const size_t smemFinal = (size_t)(2 * DIM * DOUT + 2 * 64 * DIM) * sizeof(float);  // 131072
    cudaFuncSetAttribute(k_gemm_relu,  cudaFuncAttributeMaxDynamicSharedMemorySize, (int)smemRelu);
    cudaFuncSetAttribute(k_gemm_final, cudaFuncAttributeMaxDynamicSharedMemorySize, (int)smemFinal);

    // layer 0
    k_agg<<<aggBlocks, 256>>>(x, agg, n);
    k_gemm_relu<<<gemmBlocks, 256, smemRelu>>>(agg, x, Wl0, Wr0, b0, h0, n);
    // layer 1
    k_agg<<<aggBlocks, 256>>>(h0, agg, n);
    k_gemm_relu<<<gemmBlocks, 256, smemRelu>>>(agg, h0, Wl1, Wr1, b1, h1, n);
    // layer 2 + log_softmax
    k_agg<<<aggBlocks, 256>>>(h1, agg, n);
    k_gemm_final<<<gemmBlocks, 256, smemFinal>>>(agg, h1, Wl2, Wr2, b2, out_ls, out_h, n);
}

// round 5
// speedup vs baseline: 1.6665x; 1.6665x over previous
#include <cuda_runtime.h>
#include <math.h>

#define NN 50000
#define NE 800000
#define DIM 128
#define DOUT 64

// ---- scratch (device globals: allocation-free) ----
__device__ float g_agg[NN * DIM];
__device__ float g_h0[NN * DIM];
__device__ float g_h1[NN * DIM];
__device__ int   g_cnt[NN];
__device__ int   g_rowstart[NN + 1];
__device__ int   g_cursor[NN];
__device__ int   g_srcs[NE];

// ---------------- tf32 helpers ----------------
__device__ __forceinline__ unsigned f2tf32(float f) {
    unsigned r;
    asm("cvt.rna.tf32.f32 %0, %1;" : "=r"(r) : "f"(f));
    return r;
}

__device__ __forceinline__ void mma_tf32(float d[4], const unsigned a[4], const unsigned b[2]) {
    asm("mma.sync.aligned.m16n8k8.row.col.f32.tf32.tf32.f32 "
        "{%0,%1,%2,%3}, {%4,%5,%6,%7}, {%8,%9}, {%0,%1,%2,%3};"
        : "+f"(d[0]), "+f"(d[1]), "+f"(d[2]), "+f"(d[3])
        : "r"(a[0]), "r"(a[1]), "r"(a[2]), "r"(a[3]), "r"(b[0]), "r"(b[1]));
}

// ---------------- CSR build ----------------
__global__ void k_zero_cnt(int n) {
    int i = blockIdx.x * blockDim.x + threadIdx.x;
    if (i < n) g_cnt[i] = 0;
}

__global__ void k_hist(const int* __restrict__ dst, int E) {
    int e = blockIdx.x * blockDim.x + threadIdx.x;
    if (e < E) atomicAdd(&g_cnt[dst[e]], 1);
}

__global__ void k_scan(int n) {
    __shared__ int wsum[32];
    const int tid = threadIdx.x, lane = tid & 31, wid = tid >> 5;
    int carry = 0;
    for (int base = 0; base < n; base += 1024) {
        int i = base + tid;
        int v = (i < n) ? g_cnt[i] : 0;
        int incl = v;
        #pragma unroll
        for (int o = 1; o < 32; o <<= 1) {
            int t = __shfl_up_sync(0xffffffffu, incl, o);
            if (lane >= o) incl += t;
        }
        if (lane == 31) wsum[wid] = incl;
        __syncthreads();
        if (wid == 0) {
            int s = wsum[lane];
            #pragma unroll
            for (int o = 1; o < 32; o <<= 1) {
                int t = __shfl_up_sync(0xffffffffu, s, o);
                if (lane >= o) s += t;
            }
            wsum[lane] = s;
        }
        __syncthreads();
        int excl = carry + (wid > 0 ? wsum[wid - 1] : 0) + incl - v;
        if (i < n) { g_rowstart[i] = excl; g_cursor[i] = excl; }
        int total = wsum[31];
        __syncthreads();
        carry += total;
    }
    if (tid == 0) g_rowstart[n] = carry;
}

__global__ void k_scatter(const int* __restrict__ src, const int* __restrict__ dst, int E) {
    int e = blockIdx.x * blockDim.x + threadIdx.x;
    if (e < E) {
        int p = atomicAdd(&g_cursor[dst[e]], 1);
        g_srcs[p] = src[e];
    }
}

// ---------------- mean aggregation (pull, warp per node, no fp atomics) ----------------
__global__ void k_agg(const float* __restrict__ in, float* __restrict__ outm, int n) {
    int w = (blockIdx.x * blockDim.x + threadIdx.x) >> 5;
    int lane = threadIdx.x & 31;
    if (w >= n) return;
    int rs = g_rowstart[w], re = g_rowstart[w + 1];
    float4 acc = make_float4(0.f, 0.f, 0.f, 0.f);
    for (int j = rs; j < re;) {
        int c = min(32, re - j);
        int s = (lane < c) ? g_srcs[j + lane] : 0;
        #pragma unroll 4
        for (int i = 0; i < c; i++) {
            int si = __shfl_sync(0xffffffffu, s, i);
            float4 v = *(const float4*)(in + (size_t)si * DIM + lane * 4);
            acc.x += v.x; acc.y += v.y; acc.z += v.z; acc.w += v.w;
        }
        j += c;
    }
    int deg = re - rs;
    float sc = deg > 0 ? 1.0f / (float)deg : 0.0f;
    acc.x *= sc; acc.y *= sc; acc.z *= sc; acc.w *= sc;
    *(float4*)(outm + (size_t)w * DIM + lane * 4) = acc;
}

// ---------------- tensor-core dual-GEMM + bias + relu (layers 0/1, 128->128) ----------------
// out[r,:] = relu( A1[r,:] @ Wl + A2[r,:] @ Wr + b ),  64-row tiles, mma.m16n8k8.tf32
#define WSTRIDE 136   // 128 + 8 pad: bank = (8k+n)%32 -> conflict-free B frags
#define ASTRIDE 136

__global__ void __launch_bounds__(256) k_gemm_relu(
    const float* __restrict__ A1, const float* __restrict__ A2,
    const float* __restrict__ Wl, const float* __restrict__ Wr,
    const float* __restrict__ bb, float* __restrict__ out, int n)
{
    extern __shared__ unsigned sm[];
    unsigned* sWl = sm;                         // 128 x 136
    unsigned* sWr = sWl + DIM * WSTRIDE;        // 128 x 136
    unsigned* sA1 = sWr + DIM * WSTRIDE;        // 64 x 136
    unsigned* sA2 = sA1 + 64 * ASTRIDE;         // 64 x 136
    const int tid = threadIdx.x;
    const int row0 = blockIdx.x * 64;

    // stage W (with tf32 rounding)
    for (int i = tid * 4; i < DIM * DIM; i += 1024) {
        int r = i >> 7, c = i & 127;
        float4 v = *(const float4*)(Wl + i);
        uint4 u = make_uint4(f2tf32(v.x), f2tf32(v.y), f2tf32(v.z), f2tf32(v.w));
        *(uint4*)(sWl + r * WSTRIDE + c) = u;
        v = *(const float4*)(Wr + i);
        u = make_uint4(f2tf32(v.x), f2tf32(v.y), f2tf32(v.z), f2tf32(v.w));
        *(uint4*)(sWr + r * WSTRIDE + c) = u;
    }
    // stage A tiles
    for (int i = tid * 4; i < 64 * DIM; i += 1024) {
        int r = i >> 7, c = i & 127;
        int gr = row0 + r;
        float4 v1, v2;
        if (gr < n) {
            v1 = *(const float4*)(A1 + (size_t)gr * DIM + c);
            v2 = *(const float4*)(A2 + (size_t)gr * DIM + c);
        } else {
            v1 = make_float4(0.f, 0.f, 0.f, 0.f); v2 = v1;
        }
        *(uint4*)(sA1 + r * ASTRIDE + c) =
            make_uint4(f2tf32(v1.x), f2tf32(v1.y), f2tf32(v1.z), f2tf32(v1.w));
        *(uint4*)(sA2 + r * ASTRIDE + c) =
            make_uint4(f2tf32(v2.x), f2tf32(v2.y), f2tf32(v2.z), f2tf32(v2.w));
    }
    __syncthreads();

    const int w    = tid >> 5, lane = tid & 31;
    const int wrg  = w & 3;        // row group: 16 rows each
    const int wcol = w >> 2;       // col group: 64 cols each
    const int gID  = lane >> 2, tig = lane & 3;
    const int r0   = wrg * 16;

    float acc[8][4];
    #pragma unroll
    for (int i = 0; i < 8; i++)
        #pragma unroll
        for (int j = 0; j < 4; j++) acc[i][j] = 0.f;

    #pragma unroll
    for (int kt = 0; kt < 16; kt++) {
        const int k0 = kt * 8;
        unsigned a1[4], a2[4];
        a1[0] = sA1[(r0 + gID)     * ASTRIDE + k0 + tig];
        a1[1] = sA1[(r0 + gID + 8) * ASTRIDE + k0 + tig];
        a1[2] = sA1[(r0 + gID)     * ASTRIDE + k0 + tig + 4];
        a1[3] = sA1[(r0 + gID + 8) * ASTRIDE + k0 + tig + 4];
        a2[0] = sA2[(r0 + gID)     * ASTRIDE + k0 + tig];
        a2[1] = sA2[(r0 + gID + 8) * ASTRIDE + k0 + tig];
        a2[2] = sA2[(r0 + gID)     * ASTRIDE + k0 + tig + 4];
        a2[3] = sA2[(r0 + gID + 8) * ASTRIDE + k0 + tig + 4];
        #pragma unroll
        for (int nt = 0; nt < 8; nt++) {
            const int n0 = wcol * 64 + nt * 8;
            unsigned b[2];
            b[0] = sWl[(k0 + tig)     * WSTRIDE + n0 + gID];
            b[1] = sWl[(k0 + tig + 4) * WSTRIDE + n0 + gID];
            mma_tf32(acc[nt], a1, b);
            b[0] = sWr[(k0 + tig)     * WSTRIDE + n0 + gID];
            b[1] = sWr[(k0 + tig + 4) * WSTRIDE + n0 + gID];
            mma_tf32(acc[nt], a2, b);
        }
    }

    // epilogue: bias + relu, direct global store
    #pragma unroll
    for (int nt = 0; nt < 8; nt++) {
        const int col = wcol * 64 + nt * 8 + 2 * tig;
        const float bi0 = bb[col], bi1 = bb[col + 1];
        int gr = row0 + r0 + gID;
        if (gr < n) {
            float2 o = make_float2(fmaxf(acc[nt][0] + bi0, 0.f),
                                   fmaxf(acc[nt][1] + bi1, 0.f));
            *(float2*)(out + (size_t)gr * DIM + col) = o;
        }
        gr += 8;
        if (gr < n) {
            float2 o = make_float2(fmaxf(acc[nt][2] + bi0, 0.f),
                                   fmaxf(acc[nt][3] + bi1, 0.f));
            *(float2*)(out + (size_t)gr * DIM + col) = o;
        }
    }
}

// ---------------- final layer: tensor-core dual-GEMM (128->64) + bias + log_softmax ----------------
#define W2STRIDE 72   // 64 + 8 pad
#define HSTRIDE  68

__global__ void __launch_bounds__(256) k_gemm_final(
    const float* __restrict__ A1, const float* __restrict__ A2,
    const float* __restrict__ Wl, const float* __restrict__ Wr,
    const float* __restrict__ bb,
    float* __restrict__ out_ls, float* __restrict__ out_h, int n)
{
    extern __shared__ unsigned sm[];
    unsigned* sWl = sm;                          // 128 x 72
    unsigned* sWr = sWl + DIM * W2STRIDE;        // 128 x 72
    unsigned* sA1 = sWr + DIM * W2STRIDE;        // 64 x 136
    unsigned* sA2 = sA1 + 64 * ASTRIDE;          // 64 x 136
    float*    sH  = (float*)(sA2 + 64 * ASTRIDE); // 64 x 68
    const int tid = threadIdx.x;
    const int row0 = blockIdx.x * 64;

    for (int i = tid * 4; i < DIM * DOUT; i += 1024) {
        int r = i >> 6, c = i & 63;
        float4 v = *(const float4*)(Wl + i);
        *(uint4*)(sWl + r * W2STRIDE + c) =
            make_uint4(f2tf32(v.x), f2tf32(v.y), f2tf32(v.z), f2tf32(v.w));
        v = *(const float4*)(Wr + i);
        *(uint4*)(sWr + r * W2STRIDE + c) =
            make_uint4(f2tf32(v.x), f2tf32(v.y), f2tf32(v.z), f2tf32(v.w));
    }
    for (int i = tid * 4; i < 64 * DIM; i += 1024) {
        int r = i >> 7, c = i & 127;
        int gr = row0 + r;
        float4 v1, v2;
        if (gr < n) {
            v1 = *(const float4*)(A1 + (size_t)gr * DIM + c);
            v2 = *(const float4*)(A2 + (size_t)gr * DIM + c);
        } else {
            v1 = make_float4(0.f, 0.f, 0.f, 0.f); v2 = v1;
        }
        *(uint4*)(sA1 + r * ASTRIDE + c) =
            make_uint4(f2tf32(v1.x), f2tf32(v1.y), f2tf32(v1.z), f2tf32(v1.w));
        *(uint4*)(sA2 + r * ASTRIDE + c) =
            make_uint4(f2tf32(v2.x), f2tf32(v2.y), f2tf32(v2.z), f2tf32(v2.w));
    }
    __syncthreads();

    const int w    = tid >> 5, lane = tid & 31;
    const int wrg  = w & 3;
    const int wcol = w >> 2;      // 32 cols each
    const int gID  = lane >> 2, tig = lane & 3;
    const int r0   = wrg * 16;

    float acc[4][4];
    #pragma unroll
    for (int i = 0; i < 4; i++)
        #pragma unroll
        for (int j = 0; j < 4; j++) acc[i][j] = 0.f;

    #pragma unroll
    for (int kt = 0; kt < 16; kt++) {
        const int k0 = kt * 8;
        unsigned a1[4], a2[4];
        a1[0] = sA1[(r0 + gID)     * ASTRIDE + k0 + tig];
        a1[1] = sA1[(r0 + gID + 8) * ASTRIDE + k0 + tig];
        a1[2] = sA1[(r0 + gID)     * ASTRIDE + k0 + tig + 4];
        a1[3] = sA1[(r0 + gID + 8) * ASTRIDE + k0 + tig + 4];
        a2[0] = sA2[(r0 + gID)     * ASTRIDE + k0 + tig];
        a2[1] = sA2[(r0 + gID + 8) * ASTRIDE + k0 + tig];
        a2[2] = sA2[(r0 + gID)     * ASTRIDE + k0 + tig + 4];
        a2[3] = sA2[(r0 + gID + 8) * ASTRIDE + k0 + tig + 4];
        #pragma unroll
        for (int nt = 0; nt < 4; nt++) {
            const int n0 = wcol * 32 + nt * 8;
            unsigned b[2];
            b[0] = sWl[(k0 + tig)     * W2STRIDE + n0 + gID];
            b[1] = sWl[(k0 + tig + 4) * W2STRIDE + n0 + gID];
            mma_tf32(acc[nt], a1, b);
            b[0] = sWr[(k0 + tig)     * W2STRIDE + n0 + gID];
            b[1] = sWr[(k0 + tig + 4) * W2STRIDE + n0 + gID];
            mma_tf32(acc[nt], a2, b);
        }
    }

    // write h (+bias) to smem for row-wise log_softmax
    #pragma unroll
    for (int nt = 0; nt < 4; nt++) {
        const int col = wcol * 32 + nt * 8 + 2 * tig;
        const float bi0 = bb[col], bi1 = bb[col + 1];
        *(float2*)(sH + (r0 + gID)     * HSTRIDE + col) =
            make_float2(acc[nt][0] + bi0, acc[nt][1] + bi1);
        *(float2*)(sH + (r0 + gID + 8) * HSTRIDE + col) =
            make_float2(acc[nt][2] + bi0, acc[nt][3] + bi1);
    }
    __syncthreads();

    // 4 threads per row, 16 cols each
    const int row = tid >> 2, q = tid & 3;
    float v[16];
    #pragma unroll
    for (int j = 0; j < 4; j++)
        *(float4*)(v + j * 4) = *(float4*)(sH + row * HSTRIDE + q * 16 + j * 4);

    float m = v[0];
    #pragma unroll
    for (int j = 1; j < 16; j++) m = fmaxf(m, v[j]);
    #pragma unroll
    for (int o = 1; o < 4; o <<= 1)
        m = fmaxf(m, __shfl_xor_sync(0xffffffffu, m, o, 4));

    float s = 0.f;
    #pragma unroll
    for (int j = 0; j < 16; j++) s += expf(v[j] - m);
    #pragma unroll
    for (int o = 1; o < 4; o <<= 1)
        s += __shfl_xor_sync(0xffffffffu, s, o, 4);

    const float lse = m + logf(s);
    const int gr = row0 + row;
    if (gr < n) {
        #pragma unroll
        for (int j = 0; j < 4; j++) {
            float4 ls = make_float4(v[j*4] - lse, v[j*4+1] - lse,
                                    v[j*4+2] - lse, v[j*4+3] - lse);
            *(float4*)(out_ls + (size_t)gr * DOUT + q * 16 + j * 4) = ls;
            if (out_h)
                *(float4*)(out_h + (size_t)gr * DOUT + q * 16 + j * 4) =
                    *(float4*)(v + j * 4);
        }
    }
}

// ---------------- driver ----------------
extern "C" void kernel_launch(void* const* d_in, const int* in_sizes, int n_in,
                              void* d_out, int out_size) {
    const float* x   = (const float*)d_in[0];
    const int*   ei  = (const int*)d_in[1];
    const float* Wl0 = (const float*)d_in[2];
    const float* Wr0 = (const float*)d_in[3];
    const float* b0  = (const float*)d_in[4];
    const float* Wl1 = (const float*)d_in[5];
    const float* Wr1 = (const float*)d_in[6];
    const float* b1  = (const float*)d_in[7];
    const float* Wl2 = (const float*)d_in[8];
    const float* Wr2 = (const float*)d_in[9];
    const float* b2  = (const float*)d_in[10];

    int n = in_sizes[0] / DIM;   // 50000
    int E = in_sizes[1] / 2;     // 800000
    const int* src = ei;
    const int* dst = ei + E;

    float *agg, *h0, *h1;
    cudaGetSymbolAddress((void**)&agg, g_agg);
    cudaGetSymbolAddress((void**)&h0,  g_h0);
    cudaGetSymbolAddress((void**)&h1,  g_h1);

    float* out_ls = (float*)d_out;
    float* out_h  = (out_size >= 2 * n * DOUT) ? out_ls + (size_t)n * DOUT : nullptr;

    // CSR build
    k_zero_cnt<<<(n + 255) / 256, 256>>>(n);
    k_hist<<<(E + 255) / 256, 256>>>(dst, E);
    k_scan<<<1, 1024>>>(n);
    k_scatter<<<(E + 255) / 256, 256>>>(src, dst, E);

    const int aggBlocks  = (n * 32 + 255) / 256;
    const int gemmBlocks = (n + 63) / 64;
    const size_t smemRelu  = (size_t)(2 * DIM * WSTRIDE + 2 * 64 * ASTRIDE) * 4;              // 208896
    const size_t smemFinal = (size_t)(2 * DIM * W2STRIDE + 2 * 64 * ASTRIDE) * 4
                           + (size_t)(64 * HSTRIDE) * 4;                                       // 160768
    cudaFuncSetAttribute(k_gemm_relu,  cudaFuncAttributeMaxDynamicSharedMemorySize, (int)smemRelu);
    cudaFuncSetAttribute(k_gemm_final, cudaFuncAttributeMaxDynamicSharedMemorySize, (int)smemFinal);

    // layer 0
    k_agg<<<aggBlocks, 256>>>(x, agg, n);
    k_gemm_relu<<<gemmBlocks, 256, smemRelu>>>(agg, x, Wl0, Wr0, b0, h0, n);
    // layer 1
    k_agg<<<aggBlocks, 256>>>(h0, agg, n);
    k_gemm_relu<<<gemmBlocks, 256, smemRelu>>>(agg, h0, Wl1, Wr1, b1, h1, n);
    // layer 2 + log_softmax
    k_agg<<<aggBlocks, 256>>>(h1, agg, n);
    k_gemm_final<<<gemmBlocks, 256, smemFinal>>>(agg, h1, Wl2, Wr2, b2, out_ls, out_h, n);
}